// round 11
// baseline (speedup 1.0000x reference)
#include <cuda_runtime.h>
#include <cuda_bf16.h>
#include <math.h>

// Problem constants
#define N_TOK   8192
#define DDIM    4096
#define NE      16

// Logits GEMM tiling
#define KSPLIT  16
#define KRANGE  (DDIM / KSPLIT)   // 256
#define KC      16                // K per pipeline stage
#define NITER   (KRANGE / KC)     // 16
#define TB      128               // tokens per block tile
#define XP      20                // smem row stride (floats): 80B, 16B-aligned, conflict-free

// Output layout (floats): [ l_aux | token_pos_after(2N) | token_pos_before(2N) | counts(E) | weight(2N) ]
#define OFF_AFTER   1
#define OFF_BEFORE  (1 + 2 * N_TOK)
#define OFF_CNT     (1 + 4 * N_TOK)
#define OFF_W       (1 + 4 * N_TOK + NE)

#define NBLK 128   // gate blocks of 64 tokens (128 < 148 SMs: co-resident barrier OK)
#define GT   64    // gate threads per block

// Scratch (device globals; no allocations allowed)
__device__ float    g_partial[KSPLIT][(size_t)N_TOK * NE];   // 8 MB (L2-resident)
__device__ int      g_h1[NBLK][NE];
__device__ int      g_h2[NBLK][NE];
__device__ float    g_colsum_part[NBLK][NE];
__device__ unsigned g_bar;   // ticket barrier counter (never reset; 2^32 % NBLK == 0)

__device__ __forceinline__ void cpa16(void* dst, const void* src) {
    unsigned d = (unsigned)__cvta_generic_to_shared(dst);
    asm volatile("cp.async.cg.shared.global [%0], [%1], 16;" :: "r"(d), "l"(src));
}

// ---------------------------------------------------------------------------
// Kernel 1: logits partials.  grid = (64 token tiles, 16 K-splits), 64 thr.
// 2-buffer cp.async pipeline, one barrier per iteration.
// Per-thread micro-tile: 8 tokens x 4 experts, packed f32x2 FMA.
// ---------------------------------------------------------------------------
__global__ __launch_bounds__(64) void logits_kernel(
    const float* __restrict__ x, const float* __restrict__ wg)
{
    __shared__ float xs[2][TB][XP];   // 2*128*20*4 = 20480 B
    __shared__ float ws[2][NE][XP];   // 2*16*20*4  =  2560 B

    const int tid     = threadIdx.x;
    const int tx      = tid & 3;      // expert group: experts tx*4 .. tx*4+3
    const int ty      = tid >> 2;     // token group: tokens ty + 16*r, r=0..7
    const int tokBase = blockIdx.x * TB;
    const int kBase0  = blockIdx.y * KRANGE;

    auto load_stage = [&](int c, int buf) {
        const int kb = kBase0 + c * KC;
        // x tile: 128 rows x 16 floats = 512 float4, 8 per thread
#pragma unroll
        for (int p = 0; p < 8; p++) {
            int id  = tid + p * 64;
            int row = id >> 2, col = (id & 3) * 4;
            cpa16(&xs[buf][row][col], &x[(size_t)(tokBase + row) * DDIM + kb + col]);
        }
        // w tile: 16 rows x 16 floats = 64 float4, 1 per thread
        {
            int row = tid >> 2, col = (tid & 3) * 4;
            cpa16(&ws[buf][row][col], &wg[(size_t)row * DDIM + kb + col]);
        }
        asm volatile("cp.async.commit_group;");
    };

    unsigned long long acc[32];
#pragma unroll
    for (int i = 0; i < 32; i++) acc[i] = 0ull;   // packed {0.f, 0.f}

    load_stage(0, 0);

    for (int c = 0; c < NITER; c++) {
        const int buf = c & 1;
        asm volatile("cp.async.wait_group 0;");
        __syncthreads();   // publish stage c; all reads of buf^1 (iter c-1) done
        if (c + 1 < NITER) load_stage(c + 1, buf ^ 1);

#pragma unroll
        for (int kk = 0; kk < KC / 2; kk++) {
            unsigned long long w2[4], x2[8];
#pragma unroll
            for (int j = 0; j < 4; j++)
                w2[j] = *(const unsigned long long*)&ws[buf][tx * 4 + j][kk * 2];
#pragma unroll
            for (int r = 0; r < 8; r++)
                x2[r] = *(const unsigned long long*)&xs[buf][ty + r * 16][kk * 2];
#pragma unroll
            for (int r = 0; r < 8; r++)
#pragma unroll
                for (int j = 0; j < 4; j++)
                    asm("fma.rn.f32x2 %0, %1, %2, %0;"
                        : "+l"(acc[r * 4 + j]) : "l"(x2[r]), "l"(w2[j]));
        }
    }

    // Write partials: float4 per (token, 4 experts)
#pragma unroll
    for (int r = 0; r < 8; r++) {
        float4 v;
        float* vp = (float*)&v;
#pragma unroll
        for (int j = 0; j < 4; j++) {
            unsigned long long a = acc[r * 4 + j];
            float lo = __uint_as_float((unsigned)(a & 0xffffffffull));
            float hi = __uint_as_float((unsigned)(a >> 32));
            vp[j] = lo + hi;
        }
        int tok = tokBase + ty + r * 16;
        *(float4*)&g_partial[blockIdx.y][(size_t)tok * NE + tx * 4] = v;
    }
}

// ---------------------------------------------------------------------------
// Kernel 2 (fused): reduce + softmax + top-2 + weights + ranks, grid barrier,
// scan + offsets + counts + l_aux + scatter.  grid = 128 x 64.
// All 128 blocks co-resident (< 148 SMs); ticket barrier is graph-replay safe.
// ---------------------------------------------------------------------------
__global__ __launch_bounds__(GT) void gate_fused_kernel(float* __restrict__ out)
{
    __shared__ int   wh1[2][NE], wh2[2][NE];
    __shared__ int   pre1[2][NE], pre2[2][NE];
    __shared__ float warp_sums[2][NE];
    __shared__ int   sb1[NE], sb2[NE], tot_s[NE], cnt1_s[NE];
    __shared__ float me_part[NE];

    const int tid  = threadIdx.x;
    const int lane = tid & 31;
    const int warp = tid >> 5;    // 0..1
    const int blk  = blockIdx.x;
    const int t    = blk * GT + tid;

    // ---- Phase A: reduce partials (L2-resident), softmax, top-2 ----
    float l[NE];
#pragma unroll
    for (int e = 0; e < NE; e++) l[e] = 0.0f;
#pragma unroll
    for (int s = 0; s < KSPLIT; s++) {
#pragma unroll
        for (int q = 0; q < 4; q++) {
            float4 v = *(const float4*)&g_partial[s][(size_t)t * NE + q * 4];
            l[q * 4 + 0] += v.x; l[q * 4 + 1] += v.y;
            l[q * 4 + 2] += v.z; l[q * 4 + 3] += v.w;
        }
    }

    float m = l[0];
#pragma unroll
    for (int e = 1; e < NE; e++) m = fmaxf(m, l[e]);
    float p[NE], sum = 0.0f;
#pragma unroll
    for (int e = 0; e < NE; e++) { p[e] = expf(l[e] - m); sum += p[e]; }

    // top-2 (strict > keeps lowest index, matching lax.top_k ties)
    int e1 = 0; float b1 = l[0];
#pragma unroll
    for (int e = 1; e < NE; e++) if (l[e] > b1) { b1 = l[e]; e1 = e; }
    int e2 = -1; float b2 = -3.4e38f;
#pragma unroll
    for (int e = 0; e < NE; e++) if (e != e1 && l[e] > b2) { b2 = l[e]; e2 = e; }

    float p1 = p[e1], p2 = p[e2];
    float invn = 1.0f / (p1 + p2);
    out[OFF_W + t]         = p1 * invn;
    out[OFF_W + N_TOK + t] = p2 * invn;

    // per-warp expert histograms + in-warp ranks (order-preserving)
    if (tid < 32) { ((int*)wh1)[tid] = 0; ((int*)wh2)[tid] = 0; }
    __syncthreads();

    unsigned m1  = __match_any_sync(0xffffffffu, e1);
    int      lr1 = __popc(m1 & ((1u << lane) - 1u));
    if ((__ffs(m1) - 1) == lane) wh1[warp][e1] = __popc(m1);
    unsigned m2  = __match_any_sync(0xffffffffu, e2);
    int      lr2 = __popc(m2 & ((1u << lane) - 1u));
    if ((__ffs(m2) - 1) == lane) wh2[warp][e2] = __popc(m2);
    __syncthreads();

    if (tid < NE) {
        int r = wh1[0][tid];
        pre1[0][tid] = 0; pre1[1][tid] = r;
        g_h1[blk][tid] = r + wh1[1][tid];
        r = wh2[0][tid];
        pre2[0][tid] = 0; pre2[1][tid] = r;
        g_h2[blk][tid] = r + wh2[1][tid];
    }
    __syncthreads();

    const int r1 = pre1[warp][e1] + lr1;   // in-block rank, < 64
    const int r2 = pre2[warp][e2] + lr2;

    // deterministic per-block gate column sums (for l_aux's me)
    float invs = 1.0f / sum;
#pragma unroll
    for (int e = 0; e < NE; e++) {
        float g = p[e] * invs;
#pragma unroll
        for (int off = 16; off > 0; off >>= 1)
            g += __shfl_xor_sync(0xffffffffu, g, off);
        if (lane == 0) warp_sums[warp][e] = g;
    }
    __syncthreads();
    if (tid < NE) g_colsum_part[blk][tid] = warp_sums[0][tid] + warp_sums[1][tid];

    // ---- Grid barrier (ticket-based, replay-safe) ----
    __threadfence();     // publish g_h1/g_h2/g_colsum_part
    __syncthreads();
    if (tid == 0) {
        unsigned ticket = atomicAdd(&g_bar, 1u);
        unsigned target = ticket - (ticket % NBLK) + NBLK;
        while (atomicAdd(&g_bar, 0u) < target) __nanosleep(64);
    }
    __syncthreads();
    __threadfence();     // acquire

    // ---- Phase B: decomposed scan (each block computes its own bases) ----
    if (tid < NE) {
        const int e = tid;
        int s = 0, my1 = 0, my2 = 0;
#pragma unroll 8
        for (int bb = 0; bb < NBLK; bb++) { if (bb == blk) my1 = s; s += g_h1[bb][e]; }
        cnt1_s[e] = s;                         // top-1 counts (ce numerator)
#pragma unroll 8
        for (int bb = 0; bb < NBLK; bb++) { if (bb == blk) my2 = s; s += g_h2[bb][e]; }
        tot_s[e] = s;
        sb1[e] = my1; sb2[e] = my2;
        // parallel piece of l_aux: me per expert (block-order summation)
        float me = 0.0f;
#pragma unroll 8
        for (int bb = 0; bb < NBLK; bb++) me += g_colsum_part[bb][e];
        me_part[e] = me;
    }
    __syncthreads();
    if (tid < NE) {
        int o = 0;
        for (int q = 0; q < tid; q++) o += tot_s[q];   // exclusive expert offset
        sb1[tid] += o; sb2[tid] += o;
        if (blk == 0) out[OFF_CNT + tid] = (float)tot_s[tid];
    }
    __syncthreads();

    // ---- Scatter (e/r kept in registers across the barrier) ----
    const int a1 = sb1[e1] + r1;
    const int a2 = sb2[e2] + r2;
    out[OFF_AFTER + t]         = (float)a1;
    out[OFF_AFTER + N_TOK + t] = (float)a2;
    out[OFF_BEFORE + a1]       = (float)t;            // permutation -> fills all
    out[OFF_BEFORE + a2]       = (float)(N_TOK + t);

    // ---- l_aux (block 0, thread 0 combines 16 partials) ----
    if (blk == 0 && tid == 0) {
        float laux = 0.0f;
        for (int q = 0; q < NE; q++)
            laux += (me_part[q] / (float)N_TOK) * ((float)cnt1_s[q] / (float)N_TOK);
        out[0] = laux * (float)NE;
    }
}

// ---------------------------------------------------------------------------
extern "C" void kernel_launch(void* const* d_in, const int* in_sizes, int n_in,
                              void* d_out, int out_size)
{
    const float* x  = (const float*)d_in[0];   // [8192, 4096] f32
    const float* wg = (const float*)d_in[1];   // [16, 4096] f32
    float* out = (float*)d_out;

    dim3 lgrid(N_TOK / TB, KSPLIT);            // (64, 16) = 1024 CTAs
    logits_kernel<<<lgrid, 64>>>(x, wg);
    gate_fused_kernel<<<NBLK, GT>>>(out);
}